// round 1
// baseline (speedup 1.0000x reference)
#include <cuda_runtime.h>
#include <cuda_bf16.h>
#include <math.h>

// ---------------------------------------------------------------------------
// Problem constants
// ---------------------------------------------------------------------------
#define BATCH   2
#define SEQ     2048
#define HID     2048
#define NH      16
#define NKV     4
#define DH      128
#define KVW     (NKV * DH)          // 512
#define MTOT    (BATCH * SEQ)       // 4096
#define GROUPS  (NH / NKV)          // 4

// ---------------------------------------------------------------------------
// Scratch buffers (__device__ globals; no cudaMalloc allowed)
// ---------------------------------------------------------------------------
__device__ float g_q[(size_t)MTOT * HID];   // 33.5 MB
__device__ float g_k[(size_t)MTOT * KVW];   //  8.4 MB
__device__ float g_v[(size_t)MTOT * KVW];   //  8.4 MB
__device__ float g_att[(size_t)MTOT * HID]; // 33.5 MB

// ---------------------------------------------------------------------------
// fp32 GEMM + bias:  C[M,N] = A[M,K] @ W[K,N] + b[N]
// Block tile 128x128, K-step 8, 256 threads, 8x8 per-thread register tile.
// M % 128 == 0, N % 128 == 0, K % 8 == 0 (true for all four calls).
// ---------------------------------------------------------------------------
__global__ void __launch_bounds__(256)
gemm_bias_128(const float* __restrict__ A, const float* __restrict__ W,
              const float* __restrict__ bias, float* __restrict__ C,
              int M, int N, int K)
{
    __shared__ float As[8][132];   // [k][m], padded
    __shared__ float Bs[8][132];   // [k][n], padded

    const int tid = threadIdx.x;
    const int tx  = tid & 15;       // 0..15  -> 8 cols each
    const int ty  = tid >> 4;       // 0..15  -> 8 rows each

    const int m0 = blockIdx.y * 128;
    const int n0 = blockIdx.x * 128;

    // A-tile load mapping: one float4 per thread (128 rows x 8 k)
    const int a_m  = tid >> 1;          // 0..127
    const int a_k4 = (tid & 1) * 4;     // 0 or 4
    // B-tile load mapping: one float4 per thread (8 k-rows x 128 n)
    const int b_k  = tid >> 5;          // 0..7
    const int b_n4 = (tid & 31) * 4;    // 0..124

    const float* Aptr = A + (size_t)(m0 + a_m) * K + a_k4;
    const float* Wptr = W + (size_t)b_k * N + n0 + b_n4;

    float acc[8][8];
    #pragma unroll
    for (int i = 0; i < 8; ++i)
        #pragma unroll
        for (int j = 0; j < 8; ++j) acc[i][j] = 0.f;

    for (int k0 = 0; k0 < K; k0 += 8) {
        float4 av = *(const float4*)(Aptr + k0);
        As[a_k4 + 0][a_m] = av.x;
        As[a_k4 + 1][a_m] = av.y;
        As[a_k4 + 2][a_m] = av.z;
        As[a_k4 + 3][a_m] = av.w;
        float4 bv = *(const float4*)(Wptr + (size_t)k0 * N);
        *(float4*)&Bs[b_k][b_n4] = bv;
        __syncthreads();

        #pragma unroll
        for (int kk = 0; kk < 8; ++kk) {
            float a[8], b[8];
            *(float4*)&a[0] = *(const float4*)&As[kk][ty * 8];
            *(float4*)&a[4] = *(const float4*)&As[kk][ty * 8 + 4];
            *(float4*)&b[0] = *(const float4*)&Bs[kk][tx * 8];
            *(float4*)&b[4] = *(const float4*)&Bs[kk][tx * 8 + 4];
            #pragma unroll
            for (int i = 0; i < 8; ++i)
                #pragma unroll
                for (int j = 0; j < 8; ++j)
                    acc[i][j] += a[i] * b[j];
        }
        __syncthreads();
    }

    // epilogue: add bias, store
    float bsv[8];
    #pragma unroll
    for (int j = 0; j < 8; ++j) bsv[j] = bias[n0 + tx * 8 + j];

    #pragma unroll
    for (int i = 0; i < 8; ++i) {
        const int m = m0 + ty * 8 + i;
        float* crow = C + (size_t)m * N + n0 + tx * 8;
        float4 o0, o1;
        o0.x = acc[i][0] + bsv[0]; o0.y = acc[i][1] + bsv[1];
        o0.z = acc[i][2] + bsv[2]; o0.w = acc[i][3] + bsv[3];
        o1.x = acc[i][4] + bsv[4]; o1.y = acc[i][5] + bsv[5];
        o1.z = acc[i][6] + bsv[6]; o1.w = acc[i][7] + bsv[7];
        *(float4*)(crow)     = o0;
        *(float4*)(crow + 4) = o1;
    }
}

// ---------------------------------------------------------------------------
// Flash-style causal attention (fp32), 64 q-rows x 64 k-cols tiles.
// grid = (SEQ/64, NH, BATCH), 256 threads.
// Dynamic smem layout:
//   q_s  [64][129]  (q tile)
//   kv_s [64][129]  (k tile, then v tile)
//   p_s  [64][65]   (scores / probabilities)
//   m_s[64], l_s[64], scale_s[64], mk_s[64] (int)
// ---------------------------------------------------------------------------
#define QS_STRIDE 129
#define PS_STRIDE 65

__global__ void __launch_bounds__(256)
attn_kernel(const float* __restrict__ Q, const float* __restrict__ Kg,
            const float* __restrict__ Vg, const int* __restrict__ mask,
            float* __restrict__ O)
{
    extern __shared__ float sm[];
    float* q_s     = sm;                          // 64*129
    float* kv_s    = q_s  + 64 * QS_STRIDE;       // 64*129
    float* p_s     = kv_s + 64 * QS_STRIDE;       // 64*65
    float* m_s     = p_s  + 64 * PS_STRIDE;       // 64
    float* l_s     = m_s  + 64;                   // 64
    float* scale_s = l_s  + 64;                   // 64
    int*   mk_s    = (int*)(scale_s + 64);        // 64

    const int qb  = blockIdx.x;
    const int h   = blockIdx.y;
    const int b   = blockIdx.z;
    const int tid = threadIdx.x;
    const int tx  = tid & 15;    // 0..15
    const int ty  = tid >> 4;    // 0..15

    const int kvh = h / GROUPS;
    const float scl = 0.08838834764831845f;  // 1/sqrt(128)
    const int q0 = qb * 64;

    // Load Q tile (coalesced along d)
    for (int i = tid; i < 64 * 128; i += 256) {
        const int r = i >> 7, d = i & 127;
        q_s[r * QS_STRIDE + d] =
            Q[(size_t)(b * SEQ + q0 + r) * HID + h * DH + d];
    }
    if (tid < 64) { m_s[tid] = -1e30f; l_s[tid] = 0.f; }

    float acc[4][8];
    #pragma unroll
    for (int i = 0; i < 4; ++i)
        #pragma unroll
        for (int c = 0; c < 8; ++c) acc[i][c] = 0.f;

    __syncthreads();

    for (int kb = 0; kb <= qb; ++kb) {
        const int k0 = kb * 64;

        // Load K tile
        for (int i = tid; i < 64 * 128; i += 256) {
            const int r = i >> 7, d = i & 127;
            kv_s[r * QS_STRIDE + d] =
                Kg[(size_t)(b * SEQ + k0 + r) * KVW + kvh * DH + d];
        }
        if (tid < 64) mk_s[tid] = mask[b * SEQ + k0 + tid];
        __syncthreads();

        // Scores: each thread 4 q-rows (ty*4+i) x 4 k-cols (tx*4+j)
        float s[4][4];
        #pragma unroll
        for (int i = 0; i < 4; ++i)
            #pragma unroll
            for (int j = 0; j < 4; ++j) s[i][j] = 0.f;

        #pragma unroll 8
        for (int d = 0; d < 128; ++d) {
            float qa[4], kv[4];
            #pragma unroll
            for (int i = 0; i < 4; ++i)
                qa[i] = q_s[(ty * 4 + i) * QS_STRIDE + d];
            #pragma unroll
            for (int j = 0; j < 4; ++j)
                kv[j] = kv_s[(tx * 4 + j) * QS_STRIDE + d];
            #pragma unroll
            for (int i = 0; i < 4; ++i)
                #pragma unroll
                for (int j = 0; j < 4; ++j)
                    s[i][j] += qa[i] * kv[j];
        }

        // Apply scale + causal + attention_mask, write to p_s
        #pragma unroll
        for (int i = 0; i < 4; ++i) {
            const int qr = q0 + ty * 4 + i;
            #pragma unroll
            for (int j = 0; j < 4; ++j) {
                const int kc = k0 + tx * 4 + j;
                const bool keep = (kc <= qr) && (mk_s[tx * 4 + j] != 0);
                p_s[(ty * 4 + i) * PS_STRIDE + (tx * 4 + j)] =
                    keep ? s[i][j] * scl : -1e30f;
            }
        }
        __syncthreads();

        // Online softmax per row (threads 0..63)
        if (tid < 64) {
            const float mo = m_s[tid];
            float mx = mo;
            #pragma unroll 8
            for (int c = 0; c < 64; ++c)
                mx = fmaxf(mx, p_s[tid * PS_STRIDE + c]);
            const float f = __expf(mo - mx);
            float sum = 0.f;
            #pragma unroll 8
            for (int c = 0; c < 64; ++c) {
                const float p = __expf(p_s[tid * PS_STRIDE + c] - mx);
                p_s[tid * PS_STRIDE + c] = p;
                sum += p;
            }
            m_s[tid] = mx;
            l_s[tid] = l_s[tid] * f + sum;
            scale_s[tid] = f;
        }
        __syncthreads();

        // Load V tile (overwrites K tile)
        for (int i = tid; i < 64 * 128; i += 256) {
            const int r = i >> 7, d = i & 127;
            kv_s[r * QS_STRIDE + d] =
                Vg[(size_t)(b * SEQ + k0 + r) * KVW + kvh * DH + d];
        }
        __syncthreads();

        // Rescale accumulators, then acc += P @ V
        // thread owns rows ty*4+i, cols tx*8+c
        #pragma unroll
        for (int i = 0; i < 4; ++i) {
            const float f = scale_s[ty * 4 + i];
            #pragma unroll
            for (int c = 0; c < 8; ++c) acc[i][c] *= f;
        }
        #pragma unroll 4
        for (int kk = 0; kk < 64; ++kk) {
            float pv[4], vv[8];
            #pragma unroll
            for (int i = 0; i < 4; ++i)
                pv[i] = p_s[(ty * 4 + i) * PS_STRIDE + kk];
            #pragma unroll
            for (int c = 0; c < 8; ++c)
                vv[c] = kv_s[kk * QS_STRIDE + tx * 8 + c];
            #pragma unroll
            for (int i = 0; i < 4; ++i)
                #pragma unroll
                for (int c = 0; c < 8; ++c)
                    acc[i][c] += pv[i] * vv[c];
        }
        __syncthreads();   // before next iteration overwrites kv_s
    }

    // Epilogue: divide by l, write to [b, s, h*D + d] layout
    #pragma unroll
    for (int i = 0; i < 4; ++i) {
        const int r = q0 + ty * 4 + i;
        const float inv = 1.f / l_s[ty * 4 + i];
        float* orow = O + (size_t)(b * SEQ + r) * HID + h * DH + tx * 8;
        float4 o0, o1;
        o0.x = acc[i][0] * inv; o0.y = acc[i][1] * inv;
        o0.z = acc[i][2] * inv; o0.w = acc[i][3] * inv;
        o1.x = acc[i][4] * inv; o1.y = acc[i][5] * inv;
        o1.z = acc[i][6] * inv; o1.w = acc[i][7] * inv;
        *(float4*)(orow)     = o0;
        *(float4*)(orow + 4) = o1;
    }
}

// ---------------------------------------------------------------------------
// Launch
// ---------------------------------------------------------------------------
extern "C" void kernel_launch(void* const* d_in, const int* in_sizes, int n_in,
                              void* d_out, int out_size)
{
    const float* x    = (const float*)d_in[0];
    const int*   mask = (const int*)  d_in[1];
    const float* Wq   = (const float*)d_in[2];
    const float* bq   = (const float*)d_in[3];
    const float* Wk   = (const float*)d_in[4];
    const float* bk   = (const float*)d_in[5];
    const float* Wv   = (const float*)d_in[6];
    const float* bv   = (const float*)d_in[7];
    const float* Wo   = (const float*)d_in[8];
    const float* bo   = (const float*)d_in[9];
    float* out = (float*)d_out;

    void *pq, *pk, *pv, *pa;
    cudaGetSymbolAddress(&pq, g_q);
    cudaGetSymbolAddress(&pk, g_k);
    cudaGetSymbolAddress(&pv, g_v);
    cudaGetSymbolAddress(&pa, g_att);

    dim3 blk(256);

    // QKV projections
    gemm_bias_128<<<dim3(HID / 128, MTOT / 128), blk>>>(x, Wq, bq, (float*)pq,
                                                        MTOT, HID, HID);
    gemm_bias_128<<<dim3(KVW / 128, MTOT / 128), blk>>>(x, Wk, bk, (float*)pk,
                                                        MTOT, KVW, HID);
    gemm_bias_128<<<dim3(KVW / 128, MTOT / 128), blk>>>(x, Wv, bv, (float*)pv,
                                                        MTOT, KVW, HID);

    // Attention
    const size_t smem = (size_t)(64 * QS_STRIDE * 2 + 64 * PS_STRIDE + 3 * 64) * 4
                        + 64 * sizeof(int);
    cudaFuncSetAttribute(attn_kernel, cudaFuncAttributeMaxDynamicSharedMemorySize,
                         (int)smem);
    attn_kernel<<<dim3(SEQ / 64, NH, BATCH), blk, smem>>>(
        (const float*)pq, (const float*)pk, (const float*)pv, mask, (float*)pa);

    // Output projection
    gemm_bias_128<<<dim3(HID / 128, MTOT / 128), blk>>>((const float*)pa, Wo, bo,
                                                        out, MTOT, HID, HID);
}

// round 3
// speedup vs baseline: 1.5707x; 1.5707x over previous
#include <cuda_runtime.h>
#include <cuda_bf16.h>
#include <cstdint>
#include <math.h>

// ---------------------------------------------------------------------------
// Problem constants
// ---------------------------------------------------------------------------
#define BATCH   2
#define SEQ     2048
#define HID     2048
#define NH      16
#define NKV     4
#define DH      128
#define KVW     (NKV * DH)          // 512
#define MTOT    (BATCH * SEQ)       // 4096
#define GROUPS  (NH / NKV)          // 4
#define GEMM_K  2048

// ---------------------------------------------------------------------------
// PTX helpers — ONLY non-'a' features (mma.sync / ldmatrix / cp.async).
// tcgen05 is rejected by this harness (PTX target is plain sm_103).
// ---------------------------------------------------------------------------
__device__ __forceinline__ uint32_t smem_to_u32(const void* p) {
    uint32_t a;
    asm("{ .reg .u64 t; cvta.to.shared.u64 t, %1; cvt.u32.u64 %0, t; }"
        : "=r"(a) : "l"(p));
    return a;
}
#define CP_ASYNC16(dst, src) \
    asm volatile("cp.async.cg.shared.global [%0], [%1], 16;" \
                 :: "r"(dst), "l"(src))
#define CP_COMMIT() asm volatile("cp.async.commit_group;")
#define CP_WAIT(n)  asm volatile("cp.async.wait_group %0;" :: "n"(n))

__device__ __forceinline__ void ldsm_x4(uint32_t* r, uint32_t addr) {
    asm volatile("ldmatrix.sync.aligned.m8n8.x4.shared.b16 {%0,%1,%2,%3}, [%4];"
                 : "=r"(r[0]), "=r"(r[1]), "=r"(r[2]), "=r"(r[3]) : "r"(addr));
}
__device__ __forceinline__ void mma_bf16(float* d, const uint32_t* a,
                                         const uint32_t* b) {
    asm volatile(
        "mma.sync.aligned.m16n8k16.row.col.f32.bf16.bf16.f32 "
        "{%0,%1,%2,%3}, {%4,%5,%6,%7}, {%8,%9}, {%0,%1,%2,%3};"
        : "+f"(d[0]), "+f"(d[1]), "+f"(d[2]), "+f"(d[3])
        : "r"(a[0]), "r"(a[1]), "r"(a[2]), "r"(a[3]), "r"(b[0]), "r"(b[1]));
}

// ---------------------------------------------------------------------------
// Scratch buffers (__device__ globals; no cudaMalloc allowed)
// ---------------------------------------------------------------------------
__device__ float g_q[(size_t)MTOT * HID];
__device__ float g_k[(size_t)MTOT * KVW];
__device__ float g_v[(size_t)MTOT * KVW];
__device__ __nv_bfloat16 g_xh[(size_t)MTOT * HID];
__device__ __nv_bfloat16 g_xl[(size_t)MTOT * HID];
__device__ __nv_bfloat16 g_ah[(size_t)MTOT * HID];
__device__ __nv_bfloat16 g_al[(size_t)MTOT * HID];
__device__ __nv_bfloat16 g_wqh[(size_t)HID * HID];
__device__ __nv_bfloat16 g_wql[(size_t)HID * HID];
__device__ __nv_bfloat16 g_wkh[(size_t)KVW * HID];
__device__ __nv_bfloat16 g_wkl[(size_t)KVW * HID];
__device__ __nv_bfloat16 g_wvh[(size_t)KVW * HID];
__device__ __nv_bfloat16 g_wvl[(size_t)KVW * HID];
__device__ __nv_bfloat16 g_woh[(size_t)HID * HID];
__device__ __nv_bfloat16 g_wol[(size_t)HID * HID];

// ---------------------------------------------------------------------------
// Converters
// ---------------------------------------------------------------------------
__global__ void split_kernel(const float* __restrict__ in,
                             __nv_bfloat16* __restrict__ hi,
                             __nv_bfloat16* __restrict__ lo, int n4)
{
    int i = blockIdx.x * blockDim.x + threadIdx.x;
    if (i >= n4) return;
    float4 v = ((const float4*)in)[i];
    __nv_bfloat16 h0 = __float2bfloat16(v.x);
    __nv_bfloat16 h1 = __float2bfloat16(v.y);
    __nv_bfloat16 h2 = __float2bfloat16(v.z);
    __nv_bfloat16 h3 = __float2bfloat16(v.w);
    __nv_bfloat16 l0 = __float2bfloat16(v.x - __bfloat162float(h0));
    __nv_bfloat16 l1 = __float2bfloat16(v.y - __bfloat162float(h1));
    __nv_bfloat16 l2 = __float2bfloat16(v.z - __bfloat162float(h2));
    __nv_bfloat16 l3 = __float2bfloat16(v.w - __bfloat162float(h3));
    ((__nv_bfloat162*)hi)[2*i]   = __nv_bfloat162(h0, h1);
    ((__nv_bfloat162*)hi)[2*i+1] = __nv_bfloat162(h2, h3);
    ((__nv_bfloat162*)lo)[2*i]   = __nv_bfloat162(l0, l1);
    ((__nv_bfloat162*)lo)[2*i+1] = __nv_bfloat162(l2, l3);
}

// W [K,N] fp32 row-major  ->  Th/Tl [N,K] bf16 row-major (transposed + split)
__global__ void wsplitT_kernel(const float* __restrict__ W,
                               __nv_bfloat16* __restrict__ Th,
                               __nv_bfloat16* __restrict__ Tl,
                               int K, int N)
{
    __shared__ float t[32][33];
    const int n  = blockIdx.x * 32 + threadIdx.x;
    const int kb = blockIdx.y * 32;
    #pragma unroll
    for (int j = 0; j < 32; j += 8)
        t[threadIdx.y + j][threadIdx.x] = W[(size_t)(kb + threadIdx.y + j) * N + n];
    __syncthreads();
    const int k  = kb + threadIdx.x;
    const int nb = blockIdx.x * 32;
    #pragma unroll
    for (int j = 0; j < 32; j += 8) {
        float v = t[threadIdx.x][threadIdx.y + j];
        __nv_bfloat16 h = __float2bfloat16(v);
        size_t o = (size_t)(nb + threadIdx.y + j) * K + k;
        Th[o] = h;
        Tl[o] = __float2bfloat16(v - __bfloat162float(h));
    }
}

// ---------------------------------------------------------------------------
// HMMA split-bf16 GEMM:  C[M,N] = (Ah+Al)[M,K] @ (Bh+Bl)^T[N,K] + bias
// CTA tile 128x128, K-chunk 32, 256 threads (2x4 warps, 64x32 warp tile).
// cp.async 2-stage double buffer.
// ---------------------------------------------------------------------------
#define KC        32
#define AS_STRIDE 40                      // bf16 per smem row (32 + 8 pad)
#define MAT_B     (128 * AS_STRIDE * 2)   // 10240 bytes
#define STAGE_B   (4 * MAT_B)             // 40960 bytes
#define NCHUNK    (GEMM_K / KC)           // 64

__global__ void __launch_bounds__(256)
gemm_hmma(const __nv_bfloat16* __restrict__ Ah, const __nv_bfloat16* __restrict__ Al,
          const __nv_bfloat16* __restrict__ Bh, const __nv_bfloat16* __restrict__ Bl,
          const float* __restrict__ bias, float* __restrict__ C, int N)
{
    extern __shared__ __align__(128) char smem[];
    const uint32_t smem_base = smem_to_u32(smem);
    const int tid  = threadIdx.x;
    const int warp = tid >> 5;
    const int lane = tid & 31;
    const int wm   = warp >> 2;   // 0..1 -> 64 m-rows
    const int wn   = warp & 3;    // 0..3 -> 32 n-cols
    const int m0   = blockIdx.y * 128;
    const int n0   = blockIdx.x * 128;

    const __nv_bfloat16* mats[4] = {Ah, Al, Bh, Bl};

    float acc[4][4][4];
    #pragma unroll
    for (int a = 0; a < 4; ++a)
        #pragma unroll
        for (int b = 0; b < 4; ++b)
            #pragma unroll
            for (int c = 0; c < 4; ++c) acc[a][b][c] = 0.f;

    // --- stage loader ---
    auto load_stage = [&](int s, int k0) {
        const uint32_t st = smem_base + s * STAGE_B;
        #pragma unroll
        for (int mat = 0; mat < 4; ++mat) {
            const __nv_bfloat16* src = mats[mat];
            const int r0 = (mat < 2) ? m0 : n0;
            const uint32_t dstb = st + mat * MAT_B;
            #pragma unroll
            for (int it = 0; it < 2; ++it) {
                const int idx = it * 256 + tid;
                const int row = idx >> 2;
                const int k4  = idx & 3;
                const void* sp = src + (size_t)(r0 + row) * GEMM_K + k0 + k4 * 8;
                const uint32_t dp = dstb + row * (AS_STRIDE * 2) + k4 * 16;
                CP_ASYNC16(dp, sp);
            }
        }
    };

    load_stage(0, 0);
    CP_COMMIT();

    for (int c = 0; c < NCHUNK; ++c) {
        if (c + 1 < NCHUNK) {
            load_stage((c + 1) & 1, (c + 1) * KC);
            CP_COMMIT();
            CP_WAIT(1);
        } else {
            CP_WAIT(0);
        }
        __syncthreads();

        const uint32_t stg = smem_base + (c & 1) * STAGE_B;
        const uint32_t pAh = stg;
        const uint32_t pAl = stg + MAT_B;
        const uint32_t pBh = stg + 2 * MAT_B;
        const uint32_t pBl = stg + 3 * MAT_B;

        #pragma unroll
        for (int ks = 0; ks < 2; ++ks) {
            const int kcol = ks * 16;
            uint32_t bh[8], bl[8];
            #pragma unroll
            for (int p = 0; p < 2; ++p) {
                const int nrow = wn * 32 + p * 16 + (lane & 7) + ((lane >> 4) << 3);
                const int kk   = kcol + (((lane >> 3) & 1) << 3);
                const uint32_t off = (nrow * AS_STRIDE + kk) * 2;
                ldsm_x4(&bh[p * 4], pBh + off);
                ldsm_x4(&bl[p * 4], pBl + off);
            }
            #pragma unroll
            for (int mt = 0; mt < 4; ++mt) {
                const int mrow = wm * 64 + mt * 16 + (lane & 15);
                const int kk2  = kcol + ((lane >> 4) << 3);
                const uint32_t offa = (mrow * AS_STRIDE + kk2) * 2;
                uint32_t a[4];
                ldsm_x4(a, pAh + offa);
                #pragma unroll
                for (int nt = 0; nt < 4; ++nt) mma_bf16(acc[mt][nt], a, &bh[nt * 2]);
                #pragma unroll
                for (int nt = 0; nt < 4; ++nt) mma_bf16(acc[mt][nt], a, &bl[nt * 2]);
                ldsm_x4(a, pAl + offa);
                #pragma unroll
                for (int nt = 0; nt < 4; ++nt) mma_bf16(acc[mt][nt], a, &bh[nt * 2]);
            }
        }
        __syncthreads();
    }

    // --- epilogue: bias + store ---
    #pragma unroll
    for (int mt = 0; mt < 4; ++mt)
        #pragma unroll
        for (int rh = 0; rh < 2; ++rh) {
            const int row = m0 + wm * 64 + mt * 16 + (lane >> 2) + rh * 8;
            #pragma unroll
            for (int nt = 0; nt < 4; ++nt) {
                const int col = n0 + wn * 32 + nt * 8 + (lane & 3) * 2;
                float2 v;
                v.x = acc[mt][nt][rh * 2 + 0] + bias[col];
                v.y = acc[mt][nt][rh * 2 + 1] + bias[col + 1];
                *(float2*)&C[(size_t)row * N + col] = v;
            }
        }
}

// ---------------------------------------------------------------------------
// Flash-style causal attention (fp32), 64x64 tiles. Epilogue emits bf16 hi/lo.
// ---------------------------------------------------------------------------
#define QS_STRIDE 129
#define PS_STRIDE 65

__global__ void __launch_bounds__(256)
attn_kernel(const float* __restrict__ Q, const float* __restrict__ Kg,
            const float* __restrict__ Vg, const int* __restrict__ mask,
            __nv_bfloat16* __restrict__ OH, __nv_bfloat16* __restrict__ OL)
{
    extern __shared__ float sm[];
    float* q_s     = sm;
    float* kv_s    = q_s  + 64 * QS_STRIDE;
    float* p_s     = kv_s + 64 * QS_STRIDE;
    float* m_s     = p_s  + 64 * PS_STRIDE;
    float* l_s     = m_s  + 64;
    float* scale_s = l_s  + 64;
    int*   mk_s    = (int*)(scale_s + 64);

    const int qb  = blockIdx.x;
    const int h   = blockIdx.y;
    const int b   = blockIdx.z;
    const int tid = threadIdx.x;
    const int tx  = tid & 15;
    const int ty  = tid >> 4;

    const int kvh = h / GROUPS;
    const float scl = 0.08838834764831845f;
    const int q0 = qb * 64;

    for (int i = tid; i < 64 * 128; i += 256) {
        const int r = i >> 7, d = i & 127;
        q_s[r * QS_STRIDE + d] = Q[(size_t)(b * SEQ + q0 + r) * HID + h * DH + d];
    }
    if (tid < 64) { m_s[tid] = -1e30f; l_s[tid] = 0.f; }

    float acc[4][8];
    #pragma unroll
    for (int i = 0; i < 4; ++i)
        #pragma unroll
        for (int c = 0; c < 8; ++c) acc[i][c] = 0.f;

    __syncthreads();

    for (int kb = 0; kb <= qb; ++kb) {
        const int k0 = kb * 64;

        for (int i = tid; i < 64 * 128; i += 256) {
            const int r = i >> 7, d = i & 127;
            kv_s[r * QS_STRIDE + d] = Kg[(size_t)(b * SEQ + k0 + r) * KVW + kvh * DH + d];
        }
        if (tid < 64) mk_s[tid] = mask[b * SEQ + k0 + tid];
        __syncthreads();

        float s[4][4];
        #pragma unroll
        for (int i = 0; i < 4; ++i)
            #pragma unroll
            for (int j = 0; j < 4; ++j) s[i][j] = 0.f;

        #pragma unroll 8
        for (int d = 0; d < 128; ++d) {
            float qa[4], kv[4];
            #pragma unroll
            for (int i = 0; i < 4; ++i) qa[i] = q_s[(ty * 4 + i) * QS_STRIDE + d];
            #pragma unroll
            for (int j = 0; j < 4; ++j) kv[j] = kv_s[(tx * 4 + j) * QS_STRIDE + d];
            #pragma unroll
            for (int i = 0; i < 4; ++i)
                #pragma unroll
                for (int j = 0; j < 4; ++j) s[i][j] += qa[i] * kv[j];
        }

        #pragma unroll
        for (int i = 0; i < 4; ++i) {
            const int qr = q0 + ty * 4 + i;
            #pragma unroll
            for (int j = 0; j < 4; ++j) {
                const int kc = k0 + tx * 4 + j;
                const bool keep = (kc <= qr) && (mk_s[tx * 4 + j] != 0);
                p_s[(ty * 4 + i) * PS_STRIDE + (tx * 4 + j)] = keep ? s[i][j] * scl : -1e30f;
            }
        }
        __syncthreads();

        if (tid < 64) {
            const float mo = m_s[tid];
            float mx = mo;
            #pragma unroll 8
            for (int c = 0; c < 64; ++c) mx = fmaxf(mx, p_s[tid * PS_STRIDE + c]);
            const float f = __expf(mo - mx);
            float sum = 0.f;
            #pragma unroll 8
            for (int c = 0; c < 64; ++c) {
                const float p = __expf(p_s[tid * PS_STRIDE + c] - mx);
                p_s[tid * PS_STRIDE + c] = p;
                sum += p;
            }
            m_s[tid] = mx;
            l_s[tid] = l_s[tid] * f + sum;
            scale_s[tid] = f;
        }
        __syncthreads();

        for (int i = tid; i < 64 * 128; i += 256) {
            const int r = i >> 7, d = i & 127;
            kv_s[r * QS_STRIDE + d] = Vg[(size_t)(b * SEQ + k0 + r) * KVW + kvh * DH + d];
        }
        __syncthreads();

        #pragma unroll
        for (int i = 0; i < 4; ++i) {
            const float f = scale_s[ty * 4 + i];
            #pragma unroll
            for (int c = 0; c < 8; ++c) acc[i][c] *= f;
        }
        #pragma unroll 4
        for (int kk = 0; kk < 64; ++kk) {
            float pv[4], vv[8];
            #pragma unroll
            for (int i = 0; i < 4; ++i) pv[i] = p_s[(ty * 4 + i) * PS_STRIDE + kk];
            #pragma unroll
            for (int c = 0; c < 8; ++c) vv[c] = kv_s[kk * QS_STRIDE + tx * 8 + c];
            #pragma unroll
            for (int i = 0; i < 4; ++i)
                #pragma unroll
                for (int c = 0; c < 8; ++c) acc[i][c] += pv[i] * vv[c];
        }
        __syncthreads();
    }

    // Epilogue: normalize, split to bf16 hi/lo (input for HMMA O projection)
    #pragma unroll
    for (int i = 0; i < 4; ++i) {
        const int r = q0 + ty * 4 + i;
        const float inv = 1.f / l_s[ty * 4 + i];
        const size_t base = (size_t)(b * SEQ + r) * HID + h * DH + tx * 8;
        #pragma unroll
        for (int c = 0; c < 8; ++c) {
            const float v = acc[i][c] * inv;
            const __nv_bfloat16 hv = __float2bfloat16(v);
            OH[base + c] = hv;
            OL[base + c] = __float2bfloat16(v - __bfloat162float(hv));
        }
    }
}

// ---------------------------------------------------------------------------
// Launch
// ---------------------------------------------------------------------------
extern "C" void kernel_launch(void* const* d_in, const int* in_sizes, int n_in,
                              void* d_out, int out_size)
{
    const float* x    = (const float*)d_in[0];
    const int*   mask = (const int*)  d_in[1];
    const float* Wq   = (const float*)d_in[2];
    const float* bq   = (const float*)d_in[3];
    const float* Wk   = (const float*)d_in[4];
    const float* bk   = (const float*)d_in[5];
    const float* Wv   = (const float*)d_in[6];
    const float* bv   = (const float*)d_in[7];
    const float* Wo   = (const float*)d_in[8];
    const float* bo   = (const float*)d_in[9];
    float* out = (float*)d_out;

    void *pq, *pk, *pv, *pxh, *pxl, *pah, *pal;
    void *pwqh, *pwql, *pwkh, *pwkl, *pwvh, *pwvl, *pwoh, *pwol;
    cudaGetSymbolAddress(&pq,  g_q);
    cudaGetSymbolAddress(&pk,  g_k);
    cudaGetSymbolAddress(&pv,  g_v);
    cudaGetSymbolAddress(&pxh, g_xh);
    cudaGetSymbolAddress(&pxl, g_xl);
    cudaGetSymbolAddress(&pah, g_ah);
    cudaGetSymbolAddress(&pal, g_al);
    cudaGetSymbolAddress(&pwqh, g_wqh);
    cudaGetSymbolAddress(&pwql, g_wql);
    cudaGetSymbolAddress(&pwkh, g_wkh);
    cudaGetSymbolAddress(&pwkl, g_wkl);
    cudaGetSymbolAddress(&pwvh, g_wvh);
    cudaGetSymbolAddress(&pwvl, g_wvl);
    cudaGetSymbolAddress(&pwoh, g_woh);
    cudaGetSymbolAddress(&pwol, g_wol);

    // --- converters ---
    const int n4 = MTOT * HID / 4;
    split_kernel<<<n4 / 256, 256>>>(x, (__nv_bfloat16*)pxh, (__nv_bfloat16*)pxl, n4);
    dim3 tb(32, 8);
    wsplitT_kernel<<<dim3(HID / 32, HID / 32), tb>>>(Wq, (__nv_bfloat16*)pwqh,
                                                     (__nv_bfloat16*)pwql, HID, HID);
    wsplitT_kernel<<<dim3(KVW / 32, HID / 32), tb>>>(Wk, (__nv_bfloat16*)pwkh,
                                                     (__nv_bfloat16*)pwkl, HID, KVW);
    wsplitT_kernel<<<dim3(KVW / 32, HID / 32), tb>>>(Wv, (__nv_bfloat16*)pwvh,
                                                     (__nv_bfloat16*)pwvl, HID, KVW);
    wsplitT_kernel<<<dim3(HID / 32, HID / 32), tb>>>(Wo, (__nv_bfloat16*)pwoh,
                                                     (__nv_bfloat16*)pwol, HID, HID);

    // --- HMMA projections ---
    const int gemm_smem = 2 * STAGE_B;   // 81920
    cudaFuncSetAttribute(gemm_hmma, cudaFuncAttributeMaxDynamicSharedMemorySize,
                         gemm_smem);

    gemm_hmma<<<dim3(HID / 128, MTOT / 128), 256, gemm_smem>>>(
        (const __nv_bfloat16*)pxh, (const __nv_bfloat16*)pxl,
        (const __nv_bfloat16*)pwqh, (const __nv_bfloat16*)pwql, bq, (float*)pq, HID);
    gemm_hmma<<<dim3(KVW / 128, MTOT / 128), 256, gemm_smem>>>(
        (const __nv_bfloat16*)pxh, (const __nv_bfloat16*)pxl,
        (const __nv_bfloat16*)pwkh, (const __nv_bfloat16*)pwkl, bk, (float*)pk, KVW);
    gemm_hmma<<<dim3(KVW / 128, MTOT / 128), 256, gemm_smem>>>(
        (const __nv_bfloat16*)pxh, (const __nv_bfloat16*)pxl,
        (const __nv_bfloat16*)pwvh, (const __nv_bfloat16*)pwvl, bv, (float*)pv, KVW);

    // --- attention (fp32 SIMT) ---
    const size_t smem = (size_t)(64 * QS_STRIDE * 2 + 64 * PS_STRIDE + 3 * 64) * 4
                        + 64 * sizeof(int);
    cudaFuncSetAttribute(attn_kernel, cudaFuncAttributeMaxDynamicSharedMemorySize,
                         (int)smem);
    attn_kernel<<<dim3(SEQ / 64, NH, BATCH), 256, smem>>>(
        (const float*)pq, (const float*)pk, (const float*)pv, mask,
        (__nv_bfloat16*)pah, (__nv_bfloat16*)pal);

    // --- output projection ---
    gemm_hmma<<<dim3(HID / 128, MTOT / 128), 256, gemm_smem>>>(
        (const __nv_bfloat16*)pah, (const __nv_bfloat16*)pal,
        (const __nv_bfloat16*)pwoh, (const __nv_bfloat16*)pwol, bo, out, HID);
}

// round 4
// speedup vs baseline: 3.1407x; 1.9996x over previous
#include <cuda_runtime.h>
#include <cuda_bf16.h>
#include <cstdint>
#include <math.h>

// ---------------------------------------------------------------------------
// Problem constants
// ---------------------------------------------------------------------------
#define BATCH   2
#define SEQ     2048
#define HID     2048
#define NH      16
#define NKV     4
#define DH      128
#define KVW     (NKV * DH)          // 512
#define MTOT    (BATCH * SEQ)       // 4096
#define GROUPS  (NH / NKV)          // 4
#define GEMM_K  2048

// ---------------------------------------------------------------------------
// PTX helpers — ONLY non-'a' features (mma.sync / ldmatrix / cp.async).
// ---------------------------------------------------------------------------
__device__ __forceinline__ uint32_t smem_to_u32(const void* p) {
    uint32_t a;
    asm("{ .reg .u64 t; cvta.to.shared.u64 t, %1; cvt.u32.u64 %0, t; }"
        : "=r"(a) : "l"(p));
    return a;
}
#define CP_ASYNC16(dst, src) \
    asm volatile("cp.async.cg.shared.global [%0], [%1], 16;" \
                 :: "r"(dst), "l"(src))
#define CP_ASYNC4(dst, src) \
    asm volatile("cp.async.ca.shared.global [%0], [%1], 4;" \
                 :: "r"(dst), "l"(src))
#define CP_COMMIT() asm volatile("cp.async.commit_group;")
#define CP_WAIT(n)  asm volatile("cp.async.wait_group %0;" :: "n"(n))

__device__ __forceinline__ void ldsm_x4(uint32_t* r, uint32_t addr) {
    asm volatile("ldmatrix.sync.aligned.m8n8.x4.shared.b16 {%0,%1,%2,%3}, [%4];"
                 : "=r"(r[0]), "=r"(r[1]), "=r"(r[2]), "=r"(r[3]) : "r"(addr));
}
__device__ __forceinline__ void mma_bf16(float* d, const uint32_t* a,
                                         const uint32_t* b) {
    asm volatile(
        "mma.sync.aligned.m16n8k16.row.col.f32.bf16.bf16.f32 "
        "{%0,%1,%2,%3}, {%4,%5,%6,%7}, {%8,%9}, {%0,%1,%2,%3};"
        : "+f"(d[0]), "+f"(d[1]), "+f"(d[2]), "+f"(d[3])
        : "r"(a[0]), "r"(a[1]), "r"(a[2]), "r"(a[3]), "r"(b[0]), "r"(b[1]));
}
// pack two floats to bf16x2 hi-part + residual lo-part
__device__ __forceinline__ void split2(float x, float y, uint32_t& hi, uint32_t& lo) {
    __nv_bfloat16 bx = __float2bfloat16(x), by = __float2bfloat16(y);
    __nv_bfloat162 h(bx, by);
    hi = *reinterpret_cast<uint32_t*>(&h);
    __nv_bfloat162 l(__float2bfloat16(x - __bfloat162float(bx)),
                     __float2bfloat16(y - __bfloat162float(by)));
    lo = *reinterpret_cast<uint32_t*>(&l);
}

// ---------------------------------------------------------------------------
// Scratch buffers (__device__ globals; no cudaMalloc allowed)
// ---------------------------------------------------------------------------
__device__ float g_v[(size_t)MTOT * KVW];
__device__ __nv_bfloat16 g_xh[(size_t)MTOT * HID];
__device__ __nv_bfloat16 g_xl[(size_t)MTOT * HID];
__device__ __nv_bfloat16 g_qh[(size_t)MTOT * HID];
__device__ __nv_bfloat16 g_ql[(size_t)MTOT * HID];
__device__ __nv_bfloat16 g_kh[(size_t)MTOT * KVW];
__device__ __nv_bfloat16 g_kl[(size_t)MTOT * KVW];
__device__ __nv_bfloat16 g_vth[(size_t)MTOT * KVW];   // [B*KVW, SEQ]
__device__ __nv_bfloat16 g_vtl[(size_t)MTOT * KVW];
__device__ __nv_bfloat16 g_ah[(size_t)MTOT * HID];
__device__ __nv_bfloat16 g_al[(size_t)MTOT * HID];
__device__ __nv_bfloat16 g_wqh[(size_t)HID * HID];
__device__ __nv_bfloat16 g_wql[(size_t)HID * HID];
__device__ __nv_bfloat16 g_wkh[(size_t)KVW * HID];
__device__ __nv_bfloat16 g_wkl[(size_t)KVW * HID];
__device__ __nv_bfloat16 g_wvh[(size_t)KVW * HID];
__device__ __nv_bfloat16 g_wvl[(size_t)KVW * HID];
__device__ __nv_bfloat16 g_woh[(size_t)HID * HID];
__device__ __nv_bfloat16 g_wol[(size_t)HID * HID];

// ---------------------------------------------------------------------------
// Converters
// ---------------------------------------------------------------------------
__global__ void split_kernel(const float* __restrict__ in,
                             __nv_bfloat16* __restrict__ hi,
                             __nv_bfloat16* __restrict__ lo, int n4)
{
    int i = blockIdx.x * blockDim.x + threadIdx.x;
    if (i >= n4) return;
    float4 v = ((const float4*)in)[i];
    __nv_bfloat16 h0 = __float2bfloat16(v.x);
    __nv_bfloat16 h1 = __float2bfloat16(v.y);
    __nv_bfloat16 h2 = __float2bfloat16(v.z);
    __nv_bfloat16 h3 = __float2bfloat16(v.w);
    ((__nv_bfloat162*)hi)[2*i]   = __nv_bfloat162(h0, h1);
    ((__nv_bfloat162*)hi)[2*i+1] = __nv_bfloat162(h2, h3);
    ((__nv_bfloat162*)lo)[2*i]   = __nv_bfloat162(
        __float2bfloat16(v.x - __bfloat162float(h0)),
        __float2bfloat16(v.y - __bfloat162float(h1)));
    ((__nv_bfloat162*)lo)[2*i+1] = __nv_bfloat162(
        __float2bfloat16(v.z - __bfloat162float(h2)),
        __float2bfloat16(v.w - __bfloat162float(h3)));
}

// W [K,N] fp32 row-major  ->  Th/Tl [N,K] bf16 row-major (transposed + split)
__global__ void wsplitT_kernel(const float* __restrict__ W,
                               __nv_bfloat16* __restrict__ Th,
                               __nv_bfloat16* __restrict__ Tl,
                               int K, int N)
{
    __shared__ float t[32][33];
    const int n  = blockIdx.x * 32 + threadIdx.x;
    const int kb = blockIdx.y * 32;
    #pragma unroll
    for (int j = 0; j < 32; j += 8)
        t[threadIdx.y + j][threadIdx.x] = W[(size_t)(kb + threadIdx.y + j) * N + n];
    __syncthreads();
    const int k  = kb + threadIdx.x;
    const int nb = blockIdx.x * 32;
    #pragma unroll
    for (int j = 0; j < 32; j += 8) {
        float v = t[threadIdx.x][threadIdx.y + j];
        __nv_bfloat16 h = __float2bfloat16(v);
        size_t o = (size_t)(nb + threadIdx.y + j) * K + k;
        Th[o] = h;
        Tl[o] = __float2bfloat16(v - __bfloat162float(h));
    }
}

// V [B*SEQ, KVW] fp32  ->  VT [B*KVW, SEQ] bf16 hi/lo  (per-batch transpose)
__global__ void vsplitT_kernel(const float* __restrict__ V,
                               __nv_bfloat16* __restrict__ Th,
                               __nv_bfloat16* __restrict__ Tl)
{
    __shared__ float t[32][33];
    const int n0 = blockIdx.x * 32;
    const int s0 = blockIdx.y * 32;
    const int b  = blockIdx.z;
    #pragma unroll
    for (int j = 0; j < 32; j += 8)
        t[threadIdx.y + j][threadIdx.x] =
            V[(size_t)(b * SEQ + s0 + threadIdx.y + j) * KVW + n0 + threadIdx.x];
    __syncthreads();
    #pragma unroll
    for (int j = 0; j < 32; j += 8) {
        float v = t[threadIdx.x][threadIdx.y + j];
        __nv_bfloat16 h = __float2bfloat16(v);
        size_t o = (size_t)(b * KVW + n0 + threadIdx.y + j) * SEQ + s0 + threadIdx.x;
        Th[o] = h;
        Tl[o] = __float2bfloat16(v - __bfloat162float(h));
    }
}

// ---------------------------------------------------------------------------
// HMMA split-bf16 GEMM:  C = (Ah+Al)[M,K] @ (Bh+Bl)^T[N,K] + bias
// mode 0: fp32 C.  mode 1: bf16 hi/lo split stores to Ch/Cl.
// ---------------------------------------------------------------------------
#define KC        32
#define AS_STRIDE 40
#define MAT_B     (128 * AS_STRIDE * 2)
#define STAGE_B   (4 * MAT_B)
#define NCHUNK    (GEMM_K / KC)

__global__ void __launch_bounds__(256)
gemm_hmma(const __nv_bfloat16* __restrict__ Ah, const __nv_bfloat16* __restrict__ Al,
          const __nv_bfloat16* __restrict__ Bh, const __nv_bfloat16* __restrict__ Bl,
          const float* __restrict__ bias, float* __restrict__ C,
          __nv_bfloat16* __restrict__ Ch, __nv_bfloat16* __restrict__ Cl,
          int N, int mode)
{
    extern __shared__ __align__(128) char smem[];
    const uint32_t smem_base = smem_to_u32(smem);
    const int tid  = threadIdx.x;
    const int warp = tid >> 5;
    const int lane = tid & 31;
    const int wm   = warp >> 2;
    const int wn   = warp & 3;
    const int m0   = blockIdx.y * 128;
    const int n0   = blockIdx.x * 128;

    const __nv_bfloat16* mats[4] = {Ah, Al, Bh, Bl};

    float acc[4][4][4];
    #pragma unroll
    for (int a = 0; a < 4; ++a)
        #pragma unroll
        for (int b = 0; b < 4; ++b)
            #pragma unroll
            for (int c = 0; c < 4; ++c) acc[a][b][c] = 0.f;

    auto load_stage = [&](int s, int k0) {
        const uint32_t st = smem_base + s * STAGE_B;
        #pragma unroll
        for (int mat = 0; mat < 4; ++mat) {
            const __nv_bfloat16* src = mats[mat];
            const int r0 = (mat < 2) ? m0 : n0;
            const uint32_t dstb = st + mat * MAT_B;
            #pragma unroll
            for (int it = 0; it < 2; ++it) {
                const int idx = it * 256 + tid;
                const int row = idx >> 2;
                const int k4  = idx & 3;
                const void* sp = src + (size_t)(r0 + row) * GEMM_K + k0 + k4 * 8;
                const uint32_t dp = dstb + row * (AS_STRIDE * 2) + k4 * 16;
                CP_ASYNC16(dp, sp);
            }
        }
    };

    load_stage(0, 0);
    CP_COMMIT();

    for (int c = 0; c < NCHUNK; ++c) {
        if (c + 1 < NCHUNK) {
            load_stage((c + 1) & 1, (c + 1) * KC);
            CP_COMMIT();
            CP_WAIT(1);
        } else {
            CP_WAIT(0);
        }
        __syncthreads();

        const uint32_t stg = smem_base + (c & 1) * STAGE_B;
        const uint32_t pAh = stg;
        const uint32_t pAl = stg + MAT_B;
        const uint32_t pBh = stg + 2 * MAT_B;
        const uint32_t pBl = stg + 3 * MAT_B;

        #pragma unroll
        for (int ks = 0; ks < 2; ++ks) {
            const int kcol = ks * 16;
            uint32_t bh[8], bl[8];
            #pragma unroll
            for (int p = 0; p < 2; ++p) {
                const int nrow = wn * 32 + p * 16 + (lane & 7) + ((lane >> 4) << 3);
                const int kk   = kcol + (((lane >> 3) & 1) << 3);
                const uint32_t off = (nrow * AS_STRIDE + kk) * 2;
                ldsm_x4(&bh[p * 4], pBh + off);
                ldsm_x4(&bl[p * 4], pBl + off);
            }
            #pragma unroll
            for (int mt = 0; mt < 4; ++mt) {
                const int mrow = wm * 64 + mt * 16 + (lane & 15);
                const int kk2  = kcol + ((lane >> 4) << 3);
                const uint32_t offa = (mrow * AS_STRIDE + kk2) * 2;
                uint32_t a[4];
                ldsm_x4(a, pAh + offa);
                #pragma unroll
                for (int nt = 0; nt < 4; ++nt) mma_bf16(acc[mt][nt], a, &bh[nt * 2]);
                #pragma unroll
                for (int nt = 0; nt < 4; ++nt) mma_bf16(acc[mt][nt], a, &bl[nt * 2]);
                ldsm_x4(a, pAl + offa);
                #pragma unroll
                for (int nt = 0; nt < 4; ++nt) mma_bf16(acc[mt][nt], a, &bh[nt * 2]);
            }
        }
        __syncthreads();
    }

    #pragma unroll
    for (int mt = 0; mt < 4; ++mt)
        #pragma unroll
        for (int rh = 0; rh < 2; ++rh) {
            const int row = m0 + wm * 64 + mt * 16 + (lane >> 2) + rh * 8;
            #pragma unroll
            for (int nt = 0; nt < 4; ++nt) {
                const int col = n0 + wn * 32 + nt * 8 + (lane & 3) * 2;
                const float v0 = acc[mt][nt][rh * 2 + 0] + bias[col];
                const float v1 = acc[mt][nt][rh * 2 + 1] + bias[col + 1];
                if (mode == 0) {
                    float2 v; v.x = v0; v.y = v1;
                    *(float2*)&C[(size_t)row * N + col] = v;
                } else {
                    uint32_t hi, lo;
                    split2(v0, v1, hi, lo);
                    *(uint32_t*)&Ch[(size_t)row * N + col] = hi;
                    *(uint32_t*)&Cl[(size_t)row * N + col] = lo;
                }
            }
        }
}

// ---------------------------------------------------------------------------
// HMMA FlashAttention: 128 q-rows x 64 kv tiles, 8 warps (16 q-rows each).
// Q/K split bf16 (3-term QK), P/V split bf16 (3-term PV). Softmax in regs.
// ---------------------------------------------------------------------------
#define QSTR 136
#define VSTR 72
#define SM_QH 0
#define SM_QL 34816
#define SM_KH 69632
#define SM_KL 87040
#define SM_VH 104448
#define SM_VL 122880
#define SM_MK 141312
#define ATTN_SMEM 141568

__global__ void __launch_bounds__(256)
attn_hmma(const __nv_bfloat16* __restrict__ Qh, const __nv_bfloat16* __restrict__ Ql,
          const __nv_bfloat16* __restrict__ Kh, const __nv_bfloat16* __restrict__ Kl,
          const __nv_bfloat16* __restrict__ VTh, const __nv_bfloat16* __restrict__ VTl,
          const int* __restrict__ mask,
          __nv_bfloat16* __restrict__ OH, __nv_bfloat16* __restrict__ OL)
{
    extern __shared__ __align__(128) char sm[];
    const uint32_t base = smem_to_u32(sm);
    const int tid = threadIdx.x;
    const int w    = tid >> 5;
    const int lane = tid & 31;
    const int qb = blockIdx.x, h = blockIdx.y, b = blockIdx.z;
    const int q0 = qb * 128;
    const int kvh = h >> 2;
    const int T = 2 * qb + 2;
    const float scl = 0.08838834764831845f;

    auto load_k = [&](int k0) {
        #pragma unroll
        for (int mat = 0; mat < 2; ++mat) {
            const __nv_bfloat16* src = mat ? Kl : Kh;
            const uint32_t dst = base + (mat ? SM_KL : SM_KH);
            #pragma unroll
            for (int i = 0; i < 4; ++i) {
                const int idx = i * 256 + tid;
                const int row = idx >> 4, c = idx & 15;
                CP_ASYNC16(dst + row * 272 + c * 16,
                           src + (size_t)(b * SEQ + k0 + row) * KVW + kvh * DH + c * 8);
            }
        }
        if (tid < 64)
            CP_ASYNC4(base + SM_MK + tid * 4, mask + b * SEQ + k0 + tid);
    };
    auto load_v = [&](int k0) {
        #pragma unroll
        for (int mat = 0; mat < 2; ++mat) {
            const __nv_bfloat16* src = mat ? VTl : VTh;
            const uint32_t dst = base + (mat ? SM_VL : SM_VH);
            #pragma unroll
            for (int i = 0; i < 4; ++i) {
                const int idx = i * 256 + tid;
                const int row = idx >> 3, c = idx & 7;
                CP_ASYNC16(dst + row * 144 + c * 16,
                           src + (size_t)(b * KVW + kvh * DH + row) * SEQ + k0 + c * 8);
            }
        }
    };

    // prologue: Q + K(0) + mask(0)
    #pragma unroll
    for (int mat = 0; mat < 2; ++mat) {
        const __nv_bfloat16* src = mat ? Ql : Qh;
        const uint32_t dst = base + (mat ? SM_QL : SM_QH);
        #pragma unroll
        for (int i = 0; i < 8; ++i) {
            const int idx = i * 256 + tid;
            const int row = idx >> 4, c = idx & 15;
            CP_ASYNC16(dst + row * 272 + c * 16,
                       src + (size_t)(b * SEQ + q0 + row) * HID + h * DH + c * 8);
        }
    }
    load_k(0);
    CP_COMMIT();
    CP_WAIT(0);
    __syncthreads();

    float s[8][4];
    float o[16][4];
    #pragma unroll
    for (int j = 0; j < 16; ++j)
        #pragma unroll
        for (int c = 0; c < 4; ++c) o[j][c] = 0.f;
    float m0 = -1e30f, m1 = -1e30f, l0 = 0.f, l1 = 0.f;

    const int r0g = q0 + w * 16 + (lane >> 2);
    const int r1g = r0g + 8;
    const int c0l = (lane & 3) * 2;
    const int* mk_s = (const int*)(sm + SM_MK);

    for (int t = 0; t < T; ++t) {
        const int k0 = t * 64;
        const bool active = (q0 + w * 16 + 15) >= k0;

        load_v(k0);
        CP_COMMIT();

        if (active) {
            #pragma unroll
            for (int j = 0; j < 8; ++j)
                #pragma unroll
                for (int c = 0; c < 4; ++c) s[j][c] = 0.f;

            // S = Qh*Kh + Qh*Kl + Ql*Kh
            #pragma unroll
            for (int kc = 0; kc < 8; ++kc) {
                const uint32_t offa =
                    ((w * 16 + (lane & 15)) * QSTR + kc * 16 + ((lane >> 4) << 3)) * 2;
                uint32_t ah[4], al[4];
                ldsm_x4(ah, base + SM_QH + offa);
                ldsm_x4(al, base + SM_QL + offa);
                #pragma unroll
                for (int g = 0; g < 4; ++g) {
                    const uint32_t offb =
                        ((g * 16 + (lane & 7) + ((lane >> 4) << 3)) * QSTR +
                         kc * 16 + (((lane >> 3) & 1) << 3)) * 2;
                    uint32_t bh[4], bl[4];
                    ldsm_x4(bh, base + SM_KH + offb);
                    ldsm_x4(bl, base + SM_KL + offb);
                    mma_bf16(s[2*g],   ah, &bh[0]);
                    mma_bf16(s[2*g+1], ah, &bh[2]);
                    mma_bf16(s[2*g],   ah, &bl[0]);
                    mma_bf16(s[2*g+1], ah, &bl[2]);
                    mma_bf16(s[2*g],   al, &bh[0]);
                    mma_bf16(s[2*g+1], al, &bh[2]);
                }
            }

            // mask + scale + online softmax (registers)
            float mx0 = -1e30f, mx1 = -1e30f;
            #pragma unroll
            for (int j = 0; j < 8; ++j) {
                const int cg = k0 + j * 8 + c0l;
                const int mk0 = mk_s[j * 8 + c0l];
                const int mk1 = mk_s[j * 8 + c0l + 1];
                s[j][0] = (cg     <= r0g && mk0) ? s[j][0] * scl : -1e30f;
                s[j][1] = (cg + 1 <= r0g && mk1) ? s[j][1] * scl : -1e30f;
                s[j][2] = (cg     <= r1g && mk0) ? s[j][2] * scl : -1e30f;
                s[j][3] = (cg + 1 <= r1g && mk1) ? s[j][3] * scl : -1e30f;
                mx0 = fmaxf(mx0, fmaxf(s[j][0], s[j][1]));
                mx1 = fmaxf(mx1, fmaxf(s[j][2], s[j][3]));
            }
            mx0 = fmaxf(mx0, __shfl_xor_sync(0xffffffff, mx0, 1));
            mx0 = fmaxf(mx0, __shfl_xor_sync(0xffffffff, mx0, 2));
            mx1 = fmaxf(mx1, __shfl_xor_sync(0xffffffff, mx1, 1));
            mx1 = fmaxf(mx1, __shfl_xor_sync(0xffffffff, mx1, 2));
            const float mn0 = fmaxf(m0, mx0), mn1 = fmaxf(m1, mx1);
            const float f0 = __expf(m0 - mn0), f1 = __expf(m1 - mn1);
            m0 = mn0; m1 = mn1;
            float sum0 = 0.f, sum1 = 0.f;
            #pragma unroll
            for (int j = 0; j < 8; ++j) {
                s[j][0] = __expf(s[j][0] - mn0);
                s[j][1] = __expf(s[j][1] - mn0);
                s[j][2] = __expf(s[j][2] - mn1);
                s[j][3] = __expf(s[j][3] - mn1);
                sum0 += s[j][0] + s[j][1];
                sum1 += s[j][2] + s[j][3];
            }
            sum0 += __shfl_xor_sync(0xffffffff, sum0, 1);
            sum0 += __shfl_xor_sync(0xffffffff, sum0, 2);
            sum1 += __shfl_xor_sync(0xffffffff, sum1, 1);
            sum1 += __shfl_xor_sync(0xffffffff, sum1, 2);
            l0 = l0 * f0 + sum0;
            l1 = l1 * f1 + sum1;
            #pragma unroll
            for (int j = 0; j < 16; ++j) {
                o[j][0] *= f0; o[j][1] *= f0;
                o[j][2] *= f1; o[j][3] *= f1;
            }
        }

        CP_WAIT(0);            // VT(t) ready
        __syncthreads();       // all warps done reading K(t)
        if (t + 1 < T) {
            load_k(t * 64 + 64);
            CP_COMMIT();
        }

        if (active) {
            // O += Ph*Vh + Ph*Vl + Pl*Vh
            #pragma unroll
            for (int kc = 0; kc < 4; ++kc) {
                uint32_t aph[4], apl[4];
                split2(s[2*kc][0],   s[2*kc][1],   aph[0], apl[0]);
                split2(s[2*kc][2],   s[2*kc][3],   aph[1], apl[1]);
                split2(s[2*kc+1][0], s[2*kc+1][1], aph[2], apl[2]);
                split2(s[2*kc+1][2], s[2*kc+1][3], aph[3], apl[3]);
                #pragma unroll
                for (int g = 0; g < 8; ++g) {
                    const uint32_t offb =
                        ((g * 16 + (lane & 7) + ((lane >> 4) << 3)) * VSTR +
                         kc * 16 + (((lane >> 3) & 1) << 3)) * 2;
                    uint32_t bh[4], bl[4];
                    ldsm_x4(bh, base + SM_VH + offb);
                    ldsm_x4(bl, base + SM_VL + offb);
                    mma_bf16(o[2*g],   aph, &bh[0]);
                    mma_bf16(o[2*g+1], aph, &bh[2]);
                    mma_bf16(o[2*g],   aph, &bl[0]);
                    mma_bf16(o[2*g+1], aph, &bl[2]);
                    mma_bf16(o[2*g],   apl, &bh[0]);
                    mma_bf16(o[2*g+1], apl, &bh[2]);
                }
            }
        }

        CP_WAIT(0);            // K(t+1) ready
        __syncthreads();       // all warps done reading VT(t)
    }

    // epilogue: normalize, split bf16 hi/lo, store
    const float inv0 = 1.f / l0, inv1 = 1.f / l1;
    const size_t base0 = (size_t)(b * SEQ + r0g) * HID + h * DH;
    const size_t base1 = (size_t)(b * SEQ + r1g) * HID + h * DH;
    #pragma unroll
    for (int j = 0; j < 16; ++j) {
        const int col = j * 8 + c0l;
        uint32_t hi, lo;
        split2(o[j][0] * inv0, o[j][1] * inv0, hi, lo);
        *(uint32_t*)&OH[base0 + col] = hi;
        *(uint32_t*)&OL[base0 + col] = lo;
        split2(o[j][2] * inv1, o[j][3] * inv1, hi, lo);
        *(uint32_t*)&OH[base1 + col] = hi;
        *(uint32_t*)&OL[base1 + col] = lo;
    }
}

// ---------------------------------------------------------------------------
// Launch
// ---------------------------------------------------------------------------
extern "C" void kernel_launch(void* const* d_in, const int* in_sizes, int n_in,
                              void* d_out, int out_size)
{
    const float* x    = (const float*)d_in[0];
    const int*   mask = (const int*)  d_in[1];
    const float* Wq   = (const float*)d_in[2];
    const float* bq   = (const float*)d_in[3];
    const float* Wk   = (const float*)d_in[4];
    const float* bk   = (const float*)d_in[5];
    const float* Wv   = (const float*)d_in[6];
    const float* bv   = (const float*)d_in[7];
    const float* Wo   = (const float*)d_in[8];
    const float* bo   = (const float*)d_in[9];
    float* out = (float*)d_out;

    void *pv, *pxh, *pxl, *pqh, *pql, *pkh, *pkl, *pvth, *pvtl, *pah, *pal;
    void *pwqh, *pwql, *pwkh, *pwkl, *pwvh, *pwvl, *pwoh, *pwol;
    cudaGetSymbolAddress(&pv,  g_v);
    cudaGetSymbolAddress(&pxh, g_xh);  cudaGetSymbolAddress(&pxl, g_xl);
    cudaGetSymbolAddress(&pqh, g_qh);  cudaGetSymbolAddress(&pql, g_ql);
    cudaGetSymbolAddress(&pkh, g_kh);  cudaGetSymbolAddress(&pkl, g_kl);
    cudaGetSymbolAddress(&pvth, g_vth); cudaGetSymbolAddress(&pvtl, g_vtl);
    cudaGetSymbolAddress(&pah, g_ah);  cudaGetSymbolAddress(&pal, g_al);
    cudaGetSymbolAddress(&pwqh, g_wqh); cudaGetSymbolAddress(&pwql, g_wql);
    cudaGetSymbolAddress(&pwkh, g_wkh); cudaGetSymbolAddress(&pwkl, g_wkl);
    cudaGetSymbolAddress(&pwvh, g_wvh); cudaGetSymbolAddress(&pwvl, g_wvl);
    cudaGetSymbolAddress(&pwoh, g_woh); cudaGetSymbolAddress(&pwol, g_wol);

    // --- converters ---
    const int n4 = MTOT * HID / 4;
    split_kernel<<<n4 / 256, 256>>>(x, (__nv_bfloat16*)pxh, (__nv_bfloat16*)pxl, n4);
    dim3 tb(32, 8);
    wsplitT_kernel<<<dim3(HID / 32, HID / 32), tb>>>(Wq, (__nv_bfloat16*)pwqh,
                                                     (__nv_bfloat16*)pwql, HID, HID);
    wsplitT_kernel<<<dim3(KVW / 32, HID / 32), tb>>>(Wk, (__nv_bfloat16*)pwkh,
                                                     (__nv_bfloat16*)pwkl, HID, KVW);
    wsplitT_kernel<<<dim3(KVW / 32, HID / 32), tb>>>(Wv, (__nv_bfloat16*)pwvh,
                                                     (__nv_bfloat16*)pwvl, HID, KVW);
    wsplitT_kernel<<<dim3(HID / 32, HID / 32), tb>>>(Wo, (__nv_bfloat16*)pwoh,
                                                     (__nv_bfloat16*)pwol, HID, HID);

    // --- HMMA projections ---
    const int gemm_smem = 2 * STAGE_B;
    cudaFuncSetAttribute(gemm_hmma, cudaFuncAttributeMaxDynamicSharedMemorySize,
                         gemm_smem);
    gemm_hmma<<<dim3(HID / 128, MTOT / 128), 256, gemm_smem>>>(
        (const __nv_bfloat16*)pxh, (const __nv_bfloat16*)pxl,
        (const __nv_bfloat16*)pwqh, (const __nv_bfloat16*)pwql, bq,
        nullptr, (__nv_bfloat16*)pqh, (__nv_bfloat16*)pql, HID, 1);
    gemm_hmma<<<dim3(KVW / 128, MTOT / 128), 256, gemm_smem>>>(
        (const __nv_bfloat16*)pxh, (const __nv_bfloat16*)pxl,
        (const __nv_bfloat16*)pwkh, (const __nv_bfloat16*)pwkl, bk,
        nullptr, (__nv_bfloat16*)pkh, (__nv_bfloat16*)pkl, KVW, 1);
    gemm_hmma<<<dim3(KVW / 128, MTOT / 128), 256, gemm_smem>>>(
        (const __nv_bfloat16*)pxh, (const __nv_bfloat16*)pxl,
        (const __nv_bfloat16*)pwvh, (const __nv_bfloat16*)pwvl, bv,
        (float*)pv, nullptr, nullptr, KVW, 0);

    // --- V transpose + split ---
    vsplitT_kernel<<<dim3(KVW / 32, SEQ / 32, BATCH), tb>>>(
        (const float*)pv, (__nv_bfloat16*)pvth, (__nv_bfloat16*)pvtl);

    // --- HMMA flash attention ---
    cudaFuncSetAttribute(attn_hmma, cudaFuncAttributeMaxDynamicSharedMemorySize,
                         ATTN_SMEM);
    attn_hmma<<<dim3(SEQ / 128, NH, BATCH), 256, ATTN_SMEM>>>(
        (const __nv_bfloat16*)pqh, (const __nv_bfloat16*)pql,
        (const __nv_bfloat16*)pkh, (const __nv_bfloat16*)pkl,
        (const __nv_bfloat16*)pvth, (const __nv_bfloat16*)pvtl,
        mask, (__nv_bfloat16*)pah, (__nv_bfloat16*)pal);

    // --- output projection ---
    gemm_hmma<<<dim3(HID / 128, MTOT / 128), 256, gemm_smem>>>(
        (const __nv_bfloat16*)pah, (const __nv_bfloat16*)pal,
        (const __nv_bfloat16*)pwoh, (const __nv_bfloat16*)pwol, bo,
        out, nullptr, nullptr, HID, 0);
}